// round 7
// baseline (speedup 1.0000x reference)
#include <cuda_runtime.h>
#include <cstdint>

// RecurrentCharLM: B=256, S=32, H=128, VOCAB=256, DEPTH=100, L=1.
// 128 blocks x 256 threads; block owns 2 batch rows; thread = (row, col).
// W column j in registers. KEY CHANGE vs R6: the two rows sync on ROW-SCOPED
// named barriers (bar.sync 1/2, 128) instead of __syncthreads, so their
// latency phases interleave on the FMA pipes instead of colliding.
// 8 accumulators shorten the dependent FMA chain; double-buffer parity is
// persistent across timesteps (no block-wide barrier in the main loop).

#define BATCH 256
#define SEQ   32
#define HID   128
#define VOC   256
#define DEPTH_IT 100
#define NBLK  128
#define NTHR  256

typedef unsigned long long ull;

__device__ __forceinline__ ull pack2(float lo, float hi) {
    ull r; asm("mov.b64 %0, {%1,%2};" : "=l"(r) : "f"(lo), "f"(hi)); return r;
}
__device__ __forceinline__ void unpack2(ull v, float &lo, float &hi) {
    asm("mov.b64 {%0,%1}, %2;" : "=f"(lo), "=f"(hi) : "l"(v));
}
__device__ __forceinline__ ull fma2(ull a, ull b, ull c) {
    ull d; asm("fma.rn.f32x2 %0, %1, %2, %3;" : "=l"(d) : "l"(a), "l"(b), "l"(c));
    return d;
}
__device__ __forceinline__ ull add2(ull a, ull b) {
    ull d; asm("add.rn.f32x2 %0, %1, %2;" : "=l"(d) : "l"(a), "l"(b)); return d;
}
__device__ __forceinline__ ull d2u(double x) { return __double_as_longlong(x); }
__device__ __forceinline__ void row_bar(int id) {
    asm volatile("bar.sync %0, 128;" :: "r"(id) : "memory");
}

__global__ void __launch_bounds__(NTHR, 1)
rnn_charlm_kernel(const int* __restrict__ chars,
                  const float* __restrict__ hidden,
                  const float* __restrict__ embed_w,
                  const float* __restrict__ Wg,      // (1,128,128): W[k][j]
                  const float* __restrict__ ro_w,    // (256,128)
                  const float* __restrict__ ro_b,    // (256,)
                  float* __restrict__ out, int out_size)
{
    // dynamic smem: ro_w in k-paired transposed layout
    // ro_p[(k>>1)*512 + 2*v + (k&1)] = ro_w[v][k]   (64*512 floats = 128KB)
    extern __shared__ float ro_p[];
    __shared__ __align__(16) float hs[2][2][HID];   // [buf][row][k]

    const int tid = threadIdx.x;
    const int j   = tid & 127;            // output column
    const int row = tid >> 7;             // 0 or 1  (warps 0-3 = row0, 4-7 = row1)
    const int r   = blockIdx.x * 2 + row; // global batch row
    const int bid = 1 + row;              // named barrier id (avoid 0)

    // ---- W column j into registers, packed along k: wq[m] = (W[2m][j], W[2m+1][j])
    ull wq[64];
#pragma unroll
    for (int m = 0; m < 64; ++m)
        wq[m] = pack2(Wg[(2 * m) * HID + j], Wg[(2 * m + 1) * HID + j]);

    // ---- stage ro_w into smem (coalesced global read, scattered smem write; once)
    for (int idx = tid; idx < VOC * HID; idx += NTHR) {
        int v = idx / HID, k = idx % HID;
        ro_p[(k >> 1) * 512 + 2 * v + (k & 1)] = ro_w[idx];
    }

    float h = hidden[r * HID + j];
    const float rb_lo = ro_b[j];
    const float rb_hi = ro_b[j + 128];
    __syncthreads();   // ro_p staging complete (only block-wide barrier)

    int cur = 0;       // persistent double-buffer parity

    for (int t = 0; t < SEQ; ++t) {
        // embed add (h = h + emb_t); publish into next buffer, row-scoped sync
        const int c = chars[r * SEQ + t];
        h += embed_w[c * HID + j];
        cur ^= 1;
        hs[cur][row][j] = h;
        row_bar(bid);

        // ---- 100 chained relu(h @ W) iterations
        for (int it = 0; it < DEPTH_IT; ++it) {
            const double2* p = (const double2*)hs[cur][row];
            ull a0 = 0, a1 = 0, a2 = 0, a3 = 0, a4 = 0, a5 = 0, a6 = 0, a7 = 0;
#pragma unroll
            for (int q = 0; q < 32; q += 4) {       // 16 k per step
                double2 x0 = p[q];
                double2 x1 = p[q + 1];
                double2 x2 = p[q + 2];
                double2 x3 = p[q + 3];
                a0 = fma2(d2u(x0.x), wq[2 * q],     a0);
                a1 = fma2(d2u(x0.y), wq[2 * q + 1], a1);
                a2 = fma2(d2u(x1.x), wq[2 * q + 2], a2);
                a3 = fma2(d2u(x1.y), wq[2 * q + 3], a3);
                a4 = fma2(d2u(x2.x), wq[2 * q + 4], a4);
                a5 = fma2(d2u(x2.y), wq[2 * q + 5], a5);
                a6 = fma2(d2u(x3.x), wq[2 * q + 6], a6);
                a7 = fma2(d2u(x3.y), wq[2 * q + 7], a7);
            }
            ull s = add2(add2(add2(a0, a1), add2(a2, a3)),
                         add2(add2(a4, a5), add2(a6, a7)));
            float lo, hi;
            unpack2(s, lo, hi);
            h = fmaxf(lo + hi, 0.0f);
            cur ^= 1;
            hs[cur][row][j] = h;
            row_bar(bid);
        }

        // ---- readout: logits[r][v] for v = j and v = j+128
        // Safe: reads hs[cur]; the next write to this buffer happens only after
        // every warp of this row passes the embed-store barrier above, i.e.
        // after all of them finished this readout.
        {
            const double2* p = (const double2*)hs[cur][row];
            ull A0a = 0, A0b = 0, A1a = 0, A1b = 0;
#pragma unroll
            for (int q = 0; q < 32; ++q) {          // 2 k-pairs per q
                double2 x = p[q];
                const float* b0 = &ro_p[(2 * q) * 512];
                const float* b1 = &ro_p[(2 * q + 1) * 512];
                ull ra0 = *(const ull*)&b0[2 * j];
                ull rc0 = *(const ull*)&b0[256 + 2 * j];
                ull ra1 = *(const ull*)&b1[2 * j];
                ull rc1 = *(const ull*)&b1[256 + 2 * j];
                A0a = fma2(d2u(x.x), ra0, A0a);
                A1a = fma2(d2u(x.x), rc0, A1a);
                A0b = fma2(d2u(x.y), ra1, A0b);
                A1b = fma2(d2u(x.y), rc1, A1b);
            }
            float lo, hi;
            float* o = out + (r * SEQ + t) * VOC;
            ull A0 = add2(A0a, A0b);
            ull A1 = add2(A1a, A1b);
            unpack2(A0, lo, hi); o[j]       = lo + hi + rb_lo;
            unpack2(A1, lo, hi); o[j + 128] = lo + hi + rb_hi;
        }
    }

    // ---- h_final (if the harness output includes it after the logits)
    if (out_size >= BATCH * SEQ * VOC + BATCH * HID) {
        float* hf = out + BATCH * SEQ * VOC;
        hf[r * HID + j] = h;
    }
}

extern "C" void kernel_launch(void* const* d_in, const int* in_sizes, int n_in,
                              void* d_out, int out_size)
{
    (void)in_sizes; (void)n_in;
    const int*   chars   = (const int*)d_in[0];
    const float* hidden  = (const float*)d_in[1];
    const float* embed_w = (const float*)d_in[2];
    const float* Ws      = (const float*)d_in[3];
    const float* ro_w    = (const float*)d_in[4];
    const float* ro_b    = (const float*)d_in[5];
    float* out = (float*)d_out;

    const size_t smem = 64 * 512 * sizeof(float);   // 128KB dynamic
    cudaFuncSetAttribute(rnn_charlm_kernel,
                         cudaFuncAttributeMaxDynamicSharedMemorySize, (int)smem);
    rnn_charlm_kernel<<<NBLK, NTHR, smem>>>(chars, hidden, embed_w, Ws,
                                            ro_w, ro_b, out, out_size);
}

// round 8
// speedup vs baseline: 1.0016x; 1.0016x over previous
#include <cuda_runtime.h>
#include <cstdint>

// RecurrentCharLM: B=256, S=32, H=128, VOCAB=256, DEPTH=100, L=1.
// 128 blocks x 256 threads; block owns 2 batch rows; thread = (row, col).
// W column j in registers; row-scoped named barriers (bar.sync 1/2, 128).
// KEY CHANGE vs R7: row 1's warps are given a one-time ~256-cycle dependent
// delay (64 chained exact x1.0 multiplies) before the main loop, creating a
// persistent half-iteration phase offset between the two rows. Each SMSP's
// two warps then alternate FMA/latency phases instead of stalling in lockstep.

#define BATCH 256
#define SEQ   32
#define HID   128
#define VOC   256
#define DEPTH_IT 100
#define NBLK  128
#define NTHR  256

typedef unsigned long long ull;

__device__ __forceinline__ ull pack2(float lo, float hi) {
    ull r; asm("mov.b64 %0, {%1,%2};" : "=l"(r) : "f"(lo), "f"(hi)); return r;
}
__device__ __forceinline__ void unpack2(ull v, float &lo, float &hi) {
    asm("mov.b64 {%0,%1}, %2;" : "=f"(lo), "=f"(hi) : "l"(v));
}
__device__ __forceinline__ ull fma2(ull a, ull b, ull c) {
    ull d; asm("fma.rn.f32x2 %0, %1, %2, %3;" : "=l"(d) : "l"(a), "l"(b), "l"(c));
    return d;
}
__device__ __forceinline__ ull add2(ull a, ull b) {
    ull d; asm("add.rn.f32x2 %0, %1, %2;" : "=l"(d) : "l"(a), "l"(b)); return d;
}
__device__ __forceinline__ ull d2u(double x) { return __double_as_longlong(x); }
__device__ __forceinline__ void row_bar(int id) {
    asm volatile("bar.sync %0, 128;" :: "r"(id) : "memory");
}

__global__ void __launch_bounds__(NTHR, 1)
rnn_charlm_kernel(const int* __restrict__ chars,
                  const float* __restrict__ hidden,
                  const float* __restrict__ embed_w,
                  const float* __restrict__ Wg,      // (1,128,128): W[k][j]
                  const float* __restrict__ ro_w,    // (256,128)
                  const float* __restrict__ ro_b,    // (256,)
                  float* __restrict__ out, int out_size)
{
    // dynamic smem: ro_w in k-paired transposed layout
    // ro_p[(k>>1)*512 + 2*v + (k&1)] = ro_w[v][k]   (64*512 floats = 128KB)
    extern __shared__ float ro_p[];
    __shared__ __align__(16) float hs[2][2][HID];   // [buf][row][k]

    const int tid = threadIdx.x;
    const int j   = tid & 127;            // output column
    const int row = tid >> 7;             // 0 or 1  (warps 0-3 = row0, 4-7 = row1)
    const int r   = blockIdx.x * 2 + row; // global batch row
    const int bid = 1 + row;              // named barrier id (avoid 0)

    // ---- W column j into registers, packed along k: wq[m] = (W[2m][j], W[2m+1][j])
    ull wq[64];
#pragma unroll
    for (int m = 0; m < 64; ++m)
        wq[m] = pack2(Wg[(2 * m) * HID + j], Wg[(2 * m + 1) * HID + j]);

    // ---- stage ro_w into smem (coalesced global read, scattered smem write; once)
    for (int idx = tid; idx < VOC * HID; idx += NTHR) {
        int v = idx / HID, k = idx % HID;
        ro_p[(k >> 1) * 512 + 2 * v + (k & 1)] = ro_w[idx];
    }

    float h = hidden[r * HID + j];
    const float rb_lo = ro_b[j];
    const float rb_hi = ro_b[j + 128];
    __syncthreads();   // ro_p staging complete (only block-wide barrier)

    // ---- SYMMETRY BREAKER: row1 delayed ~256 cyc by a dependent chain of
    // exact x1.0 multiplies (bitwise identity). Creates a persistent phase
    // offset so the two rows' FMA phases interleave on each SMSP.
    if (row == 1) {
        const float one = __int_as_float(0x3f800000);
        float d = h;
#pragma unroll
        for (int i = 0; i < 64; ++i)
            asm volatile("mul.f32 %0, %0, %1;" : "+f"(d) : "f"(one));
        h = d;
    }

    int cur = 0;       // persistent double-buffer parity

    for (int t = 0; t < SEQ; ++t) {
        // embed add (h = h + emb_t); publish into next buffer, row-scoped sync
        const int c = chars[r * SEQ + t];
        h += embed_w[c * HID + j];
        cur ^= 1;
        hs[cur][row][j] = h;
        row_bar(bid);

        // ---- 100 chained relu(h @ W) iterations
        for (int it = 0; it < DEPTH_IT; ++it) {
            const double2* p = (const double2*)hs[cur][row];
            ull a0 = 0, a1 = 0, a2 = 0, a3 = 0, a4 = 0, a5 = 0, a6 = 0, a7 = 0;
#pragma unroll
            for (int q = 0; q < 32; q += 4) {       // 16 k per step
                double2 x0 = p[q];
                double2 x1 = p[q + 1];
                double2 x2 = p[q + 2];
                double2 x3 = p[q + 3];
                a0 = fma2(d2u(x0.x), wq[2 * q],     a0);
                a1 = fma2(d2u(x0.y), wq[2 * q + 1], a1);
                a2 = fma2(d2u(x1.x), wq[2 * q + 2], a2);
                a3 = fma2(d2u(x1.y), wq[2 * q + 3], a3);
                a4 = fma2(d2u(x2.x), wq[2 * q + 4], a4);
                a5 = fma2(d2u(x2.y), wq[2 * q + 5], a5);
                a6 = fma2(d2u(x3.x), wq[2 * q + 6], a6);
                a7 = fma2(d2u(x3.y), wq[2 * q + 7], a7);
            }
            ull s = add2(add2(add2(a0, a1), add2(a2, a3)),
                         add2(add2(a4, a5), add2(a6, a7)));
            float lo, hi;
            unpack2(s, lo, hi);
            h = fmaxf(lo + hi, 0.0f);
            cur ^= 1;
            hs[cur][row][j] = h;
            row_bar(bid);
        }

        // ---- readout: logits[r][v] for v = j and v = j+128
        // Safe: reads hs[cur]; the next write to this buffer happens only after
        // every warp of this row passes the embed-store barrier above.
        {
            const double2* p = (const double2*)hs[cur][row];
            ull A0a = 0, A0b = 0, A1a = 0, A1b = 0;
#pragma unroll
            for (int q = 0; q < 32; ++q) {          // 2 k-pairs per q
                double2 x = p[q];
                const float* b0 = &ro_p[(2 * q) * 512];
                const float* b1 = &ro_p[(2 * q + 1) * 512];
                ull ra0 = *(const ull*)&b0[2 * j];
                ull rc0 = *(const ull*)&b0[256 + 2 * j];
                ull ra1 = *(const ull*)&b1[2 * j];
                ull rc1 = *(const ull*)&b1[256 + 2 * j];
                A0a = fma2(d2u(x.x), ra0, A0a);
                A1a = fma2(d2u(x.x), rc0, A1a);
                A0b = fma2(d2u(x.y), ra1, A0b);
                A1b = fma2(d2u(x.y), rc1, A1b);
            }
            float lo, hi;
            float* o = out + (r * SEQ + t) * VOC;
            ull A0 = add2(A0a, A0b);
            ull A1 = add2(A1a, A1b);
            unpack2(A0, lo, hi); o[j]       = lo + hi + rb_lo;
            unpack2(A1, lo, hi); o[j + 128] = lo + hi + rb_hi;
        }
    }

    // ---- h_final (if the harness output includes it after the logits)
    if (out_size >= BATCH * SEQ * VOC + BATCH * HID) {
        float* hf = out + BATCH * SEQ * VOC;
        hf[r * HID + j] = h;
    }
}

extern "C" void kernel_launch(void* const* d_in, const int* in_sizes, int n_in,
                              void* d_out, int out_size)
{
    (void)in_sizes; (void)n_in;
    const int*   chars   = (const int*)d_in[0];
    const float* hidden  = (const float*)d_in[1];
    const float* embed_w = (const float*)d_in[2];
    const float* Ws      = (const float*)d_in[3];
    const float* ro_w    = (const float*)d_in[4];
    const float* ro_b    = (const float*)d_in[5];
    float* out = (float*)d_out;

    const size_t smem = 64 * 512 * sizeof(float);   // 128KB dynamic
    cudaFuncSetAttribute(rnn_charlm_kernel,
                         cudaFuncAttributeMaxDynamicSharedMemorySize, (int)smem);
    rnn_charlm_kernel<<<NBLK, NTHR, smem>>>(chars, hidden, embed_w, Ws,
                                            ro_w, ro_b, out, out_size);
}

// round 9
// speedup vs baseline: 1.2525x; 1.2504x over previous
#include <cuda_runtime.h>
#include <cstdint>

// RecurrentCharLM: B=256, S=32, H=128, VOCAB=256, DEPTH=100, L=1.
// 128 blocks x 256 threads. Thread = (row, col-pair p, k-half s):
//   computes cols 2p,2p+1 over 64 k values; partner lane (shfl_xor 16)
//   holds the other k-half; partials combine via one 64-bit shuffle + add.
// W: 2 cols x 64 k in 128 registers (k-packed f32x2 pairs).
// h: each thread loads only its 256B k-half -> halves per-SM L1TEX
// wavefront traffic vs R5-R8 (the invariant bottleneck: L1=68.6%).
// k-half 1 stored at +272B (16B pad) so the two half-warp broadcast
// addresses hit disjoint shared-memory banks.

#define BATCH 256
#define SEQ   32
#define HID   128
#define VOC   256
#define DEPTH_IT 100
#define NBLK  128
#define NTHR  256
#define HPITCH 272     // byte offset of k=64..127 half inside a row buffer
#define HROW   544     // bytes per row buffer (2 halves, padded)

typedef unsigned long long ull;

__device__ __forceinline__ ull pack2(float lo, float hi) {
    ull r; asm("mov.b64 %0, {%1,%2};" : "=l"(r) : "f"(lo), "f"(hi)); return r;
}
__device__ __forceinline__ void unpack2(ull v, float &lo, float &hi) {
    asm("mov.b64 {%0,%1}, %2;" : "=f"(lo), "=f"(hi) : "l"(v));
}
__device__ __forceinline__ ull fma2(ull a, ull b, ull c) {
    ull d; asm("fma.rn.f32x2 %0, %1, %2, %3;" : "=l"(d) : "l"(a), "l"(b), "l"(c));
    return d;
}
__device__ __forceinline__ ull add2(ull a, ull b) {
    ull d; asm("add.rn.f32x2 %0, %1, %2;" : "=l"(d) : "l"(a), "l"(b)); return d;
}
__device__ __forceinline__ ull d2u(double x) { return __double_as_longlong(x); }

__global__ void __launch_bounds__(NTHR, 1)
rnn_charlm_kernel(const int* __restrict__ chars,
                  const float* __restrict__ hidden,
                  const float* __restrict__ embed_w,
                  const float* __restrict__ Wg,      // (1,128,128): W[k][j]
                  const float* __restrict__ ro_w,    // (256,128)
                  const float* __restrict__ ro_b,    // (256,)
                  float* __restrict__ out, int out_size)
{
    // dynamic smem: ro_w in k-paired transposed layout
    // ro_p[(k>>1)*512 + 2*v + (k&1)] = ro_w[v][k]   (64*512 floats = 128KB)
    extern __shared__ float ro_p[];
    __shared__ __align__(16) char hsraw[2][2][HROW];   // [buf][row][bytes]

    const int tid = threadIdx.x;
    const int row = tid >> 7;               // 0 or 1
    const int w   = (tid >> 5) & 3;         // warp within row
    const int l   = tid & 31;               // lane
    const int s   = l >> 4;                 // k-half (0: k<64, 1: k>=64)
    const int p   = w * 16 + (l & 15);      // col-pair index 0..63
    const int cA  = 2 * p;
    const int cB  = 2 * p + 1;
    const int R   = blockIdx.x * 2 + row;   // global batch row
    const int j   = w * 32 + l;             // readout col id 0..127
    const int ks  = s * 64;                 // my k-range start

    // ---- W: 2 columns x my 64 k's, k-packed: wA[i] = (W[ks+2i][cA], W[ks+2i+1][cA])
    ull wA[32], wB[32];
#pragma unroll
    for (int i = 0; i < 32; ++i) {
        wA[i] = pack2(Wg[(ks + 2 * i) * HID + cA], Wg[(ks + 2 * i + 1) * HID + cA]);
        wB[i] = pack2(Wg[(ks + 2 * i) * HID + cB], Wg[(ks + 2 * i + 1) * HID + cB]);
    }

    // ---- stage ro_w into smem (once)
    for (int idx = tid; idx < VOC * HID; idx += NTHR) {
        int v = idx / HID, k = idx % HID;
        ro_p[(k >> 1) * 512 + 2 * v + (k & 1)] = ro_w[idx];
    }

    float hA = hidden[R * HID + cA];
    float hB = hidden[R * HID + cB];
    const float rb_lo = ro_b[j];
    const float rb_hi = ro_b[j + 128];
    __syncthreads();

    // smem byte offset where this thread's (cA,cB) pair lives (pair never straddles halves)
    const int hoff = (cA < 64) ? cA * 4 : HPITCH + (cA - 64) * 4;

    int cur = 0;
    for (int t = 0; t < SEQ; ++t) {
        // embed add; publish into next buffer (only s==0 lanes store)
        const int c = chars[R * SEQ + t];
        hA += embed_w[c * HID + cA];
        hB += embed_w[c * HID + cB];
        cur ^= 1;
        if (s == 0) *(ull*)(hsraw[cur][row] + hoff) = pack2(hA, hB);
        __syncthreads();

        // ---- 100 chained relu(h @ W) iterations
        for (int it = 0; it < DEPTH_IT; ++it) {
            const double2* pa = (const double2*)(hsraw[cur][row] + s * HPITCH);
            ull a0 = 0, a1 = 0, b0 = 0, b1 = 0;
#pragma unroll
            for (int q = 0; q < 16; ++q) {          // 4 k per q
                double2 x = pa[q];                  // (h[k],h[k+1]) | (h[k+2],h[k+3])
                a0 = fma2(d2u(x.x), wA[2 * q],     a0);
                b0 = fma2(d2u(x.x), wB[2 * q],     b0);
                a1 = fma2(d2u(x.y), wA[2 * q + 1], a1);
                b1 = fma2(d2u(x.y), wB[2 * q + 1], b1);
            }
            ull sA = add2(a0, a1);
            ull sB = add2(b0, b1);
            // combine the two k-halves: partner lane is l ^ 16 (same warp)
            sA = add2(sA, __shfl_xor_sync(0xffffffffu, sA, 16));
            sB = add2(sB, __shfl_xor_sync(0xffffffffu, sB, 16));
            float lo, hi;
            unpack2(sA, lo, hi); hA = fmaxf(lo + hi, 0.0f);
            unpack2(sB, lo, hi); hB = fmaxf(lo + hi, 0.0f);
            cur ^= 1;
            if (s == 0) *(ull*)(hsraw[cur][row] + hoff) = pack2(hA, hB);
            __syncthreads();
        }

        // ---- readout: logits[R][v] for v = j and v = j+128 (reads padded h)
        {
            const double2* p0 = (const double2*)(hsraw[cur][row]);            // k 0..63
            const double2* p1 = (const double2*)(hsraw[cur][row] + HPITCH);   // k 64..127
            ull A0a = 0, A0b = 0, A1a = 0, A1b = 0;
#pragma unroll
            for (int q = 0; q < 32; ++q) {          // quad q covers k = 4q..4q+3
                double2 x = (q < 16) ? p0[q] : p1[q - 16];
                const float* b0 = &ro_p[(2 * q) * 512];
                const float* b1 = &ro_p[(2 * q + 1) * 512];
                ull ra0 = *(const ull*)&b0[2 * j];
                ull rc0 = *(const ull*)&b0[256 + 2 * j];
                ull ra1 = *(const ull*)&b1[2 * j];
                ull rc1 = *(const ull*)&b1[256 + 2 * j];
                A0a = fma2(d2u(x.x), ra0, A0a);
                A1a = fma2(d2u(x.x), rc0, A1a);
                A0b = fma2(d2u(x.y), ra1, A0b);
                A1b = fma2(d2u(x.y), rc1, A1b);
            }
            float lo, hi;
            float* o = out + (R * SEQ + t) * VOC;
            ull A0 = add2(A0a, A0b);
            ull A1 = add2(A1a, A1b);
            unpack2(A0, lo, hi); o[j]       = lo + hi + rb_lo;
            unpack2(A1, lo, hi); o[j + 128] = lo + hi + rb_hi;
        }
        // next timestep's embed-store targets the OTHER buffer; its barrier
        // orders the subsequent in-loop writes against these readout reads.
    }

    // ---- h_final (if the harness output includes it after the logits)
    if (out_size >= BATCH * SEQ * VOC + BATCH * HID) {
        float* hf = out + BATCH * SEQ * VOC;
        if (s == 0) {
            hf[R * HID + cA] = hA;
            hf[R * HID + cB] = hB;
        }
    }
}

extern "C" void kernel_launch(void* const* d_in, const int* in_sizes, int n_in,
                              void* d_out, int out_size)
{
    (void)in_sizes; (void)n_in;
    const int*   chars   = (const int*)d_in[0];
    const float* hidden  = (const float*)d_in[1];
    const float* embed_w = (const float*)d_in[2];
    const float* Ws      = (const float*)d_in[3];
    const float* ro_w    = (const float*)d_in[4];
    const float* ro_b    = (const float*)d_in[5];
    float* out = (float*)d_out;

    const size_t smem = 64 * 512 * sizeof(float);   // 128KB dynamic
    cudaFuncSetAttribute(rnn_charlm_kernel,
                         cudaFuncAttributeMaxDynamicSharedMemorySize, (int)smem);
    rnn_charlm_kernel<<<NBLK, NTHR, smem>>>(chars, hidden, embed_w, Ws,
                                            ro_w, ro_b, out, out_size);
}

// round 10
// speedup vs baseline: 1.3154x; 1.0502x over previous
#include <cuda_runtime.h>
#include <cstdint>

// RecurrentCharLM: B=256, S=32, H=128, VOCAB=256, DEPTH=100, L=1.
// 128 blocks x 256 threads. Thread = (row, col-quad p, k-quarter s2):
//   computes cols 4p..4p+3 over its 32-k quarter; the 4 k-quarters
//   (lanes l, l^8, l^16, l^24) combine via two float shuffle rounds.
// W: 4 cols x 32 k in 128 registers (k-packed f32x2) -- same count as R9.
// h: each thread loads only 128B (8 LDS.128) -- halves R9's L1TEX traffic,
//   which was the binding resource (R9: halving it bought -16%).
// k-quarters stored at 144B pitch -> the 4 broadcast groups are bank-disjoint.
// Row-scoped named barriers (bar.sync 1/2, 128) instead of __syncthreads.

#define BATCH 256
#define SEQ   32
#define HID   128
#define VOC   256
#define DEPTH_IT 100
#define NBLK  128
#define NTHR  256
#define QP    144          // byte pitch between k-quarters in a row buffer
#define HROW  (4*QP)       // 576 bytes per row buffer

typedef unsigned long long ull;

__device__ __forceinline__ ull pack2(float lo, float hi) {
    ull r; asm("mov.b64 %0, {%1,%2};" : "=l"(r) : "f"(lo), "f"(hi)); return r;
}
__device__ __forceinline__ void unpack2(ull v, float &lo, float &hi) {
    asm("mov.b64 {%0,%1}, %2;" : "=f"(lo), "=f"(hi) : "l"(v));
}
__device__ __forceinline__ ull fma2(ull a, ull b, ull c) {
    ull d; asm("fma.rn.f32x2 %0, %1, %2, %3;" : "=l"(d) : "l"(a), "l"(b), "l"(c));
    return d;
}
__device__ __forceinline__ ull add2(ull a, ull b) {
    ull d; asm("add.rn.f32x2 %0, %1, %2;" : "=l"(d) : "l"(a), "l"(b)); return d;
}
__device__ __forceinline__ ull d2u(double x) { return __double_as_longlong(x); }
__device__ __forceinline__ void row_bar(int id) {
    asm volatile("bar.sync %0, 128;" :: "r"(id) : "memory");
}
// reduce f32x2 accumulator to scalar, then sum across the 4 k-quarter lanes
__device__ __forceinline__ float quad_reduce(ull s) {
    float lo, hi; unpack2(s, lo, hi);
    float f = lo + hi;
    f += __shfl_xor_sync(0xffffffffu, f, 8);
    f += __shfl_xor_sync(0xffffffffu, f, 16);
    return f;
}

__global__ void __launch_bounds__(NTHR, 1)
rnn_charlm_kernel(const int* __restrict__ chars,
                  const float* __restrict__ hidden,
                  const float* __restrict__ embed_w,
                  const float* __restrict__ Wg,      // (1,128,128): W[k][j]
                  const float* __restrict__ ro_w,    // (256,128)
                  const float* __restrict__ ro_b,    // (256,)
                  float* __restrict__ out, int out_size)
{
    // dynamic smem: ro_w in k-paired transposed layout
    // ro_p[(k>>1)*512 + 2*v + (k&1)] = ro_w[v][k]   (64*512 floats = 128KB)
    extern __shared__ float ro_p[];
    __shared__ __align__(16) char hsraw[2][2][HROW];   // [buf][row][bytes]

    const int tid = threadIdx.x;
    const int row = tid >> 7;               // 0 or 1
    const int w   = (tid >> 5) & 3;         // warp within row
    const int l   = tid & 31;               // lane
    const int s2  = l >> 3;                 // k-quarter 0..3
    const int p   = w * 8 + (l & 7);        // col-quad index 0..31
    const int c0  = 4 * p;                  // first of 4 columns
    const int R   = blockIdx.x * 2 + row;   // global batch row
    const int j   = w * 32 + l;             // readout col id 0..127
    const int ks  = s2 * 32;                // my k-range start
    const int bid = 1 + row;                // named barrier id

    // ---- W: 4 columns x my 32 k's, k-packed: wA[i] = (W[ks+2i][c0], W[ks+2i+1][c0])
    ull wA[16], wB[16], wC[16], wD[16];
#pragma unroll
    for (int i = 0; i < 16; ++i) {
        const float* r0 = &Wg[(ks + 2 * i) * HID];
        const float* r1 = &Wg[(ks + 2 * i + 1) * HID];
        wA[i] = pack2(r0[c0],     r1[c0]);
        wB[i] = pack2(r0[c0 + 1], r1[c0 + 1]);
        wC[i] = pack2(r0[c0 + 2], r1[c0 + 2]);
        wD[i] = pack2(r0[c0 + 3], r1[c0 + 3]);
    }

    // ---- stage ro_w into smem (once)
    for (int idx = tid; idx < VOC * HID; idx += NTHR) {
        int v = idx / HID, k = idx % HID;
        ro_p[(k >> 1) * 512 + 2 * v + (k & 1)] = ro_w[idx];
    }

    float hA = hidden[R * HID + c0];
    float hB = hidden[R * HID + c0 + 1];
    float hC = hidden[R * HID + c0 + 2];
    float hD = hidden[R * HID + c0 + 3];
    const float rb_lo = ro_b[j];
    const float rb_hi = ro_b[j + 128];
    __syncthreads();   // ro_p staged

    // smem byte offset of this thread's 4 columns (quad never straddles a quarter)
    const int hoff = (c0 >> 5) * QP + (c0 & 31) * 4;

    int cur = 0;
    for (int t = 0; t < SEQ; ++t) {
        // embed add; publish into next buffer (one lane-octet per warp stores)
        const int c = chars[R * SEQ + t];
        const float* em = &embed_w[c * HID + c0];
        hA += em[0]; hB += em[1]; hC += em[2]; hD += em[3];
        cur ^= 1;
        if (l < 8) {
            float4 v4 = make_float4(hA, hB, hC, hD);
            *(float4*)(hsraw[cur][row] + hoff) = v4;
        }
        row_bar(bid);

        // ---- 100 chained relu(h @ W) iterations
        for (int it = 0; it < DEPTH_IT; ++it) {
            const double2* pa = (const double2*)(hsraw[cur][row] + s2 * QP);
            ull aE = 0, aO = 0, bE = 0, bO = 0, cE = 0, cO = 0, dE = 0, dO = 0;
#pragma unroll
            for (int q = 0; q < 8; ++q) {        // 4 k per q
                double2 x = pa[q];               // k = ks+4q .. ks+4q+3
                aE = fma2(d2u(x.x), wA[2 * q],     aE);
                bE = fma2(d2u(x.x), wB[2 * q],     bE);
                cE = fma2(d2u(x.x), wC[2 * q],     cE);
                dE = fma2(d2u(x.x), wD[2 * q],     dE);
                aO = fma2(d2u(x.y), wA[2 * q + 1], aO);
                bO = fma2(d2u(x.y), wB[2 * q + 1], bO);
                cO = fma2(d2u(x.y), wC[2 * q + 1], cO);
                dO = fma2(d2u(x.y), wD[2 * q + 1], dO);
            }
            hA = fmaxf(quad_reduce(add2(aE, aO)), 0.0f);
            hB = fmaxf(quad_reduce(add2(bE, bO)), 0.0f);
            hC = fmaxf(quad_reduce(add2(cE, cO)), 0.0f);
            hD = fmaxf(quad_reduce(add2(dE, dO)), 0.0f);
            cur ^= 1;
            if (l < 8) {
                float4 v4 = make_float4(hA, hB, hC, hD);
                *(float4*)(hsraw[cur][row] + hoff) = v4;
            }
            row_bar(bid);
        }

        // ---- readout: logits[R][v] for v = j and v = j+128 (quarter-padded h)
        {
            const char* hb = hsraw[cur][row];
            ull A0a = 0, A0b = 0, A1a = 0, A1b = 0;
#pragma unroll
            for (int q = 0; q < 32; ++q) {       // quad q covers k = 4q..4q+3
                double2 x = *(const double2*)(hb + (q >> 3) * QP + (q & 7) * 16);
                const float* b0 = &ro_p[(2 * q) * 512];
                const float* b1 = &ro_p[(2 * q + 1) * 512];
                ull ra0 = *(const ull*)&b0[2 * j];
                ull rc0 = *(const ull*)&b0[256 + 2 * j];
                ull ra1 = *(const ull*)&b1[2 * j];
                ull rc1 = *(const ull*)&b1[256 + 2 * j];
                A0a = fma2(d2u(x.x), ra0, A0a);
                A1a = fma2(d2u(x.x), rc0, A1a);
                A0b = fma2(d2u(x.y), ra1, A0b);
                A1b = fma2(d2u(x.y), rc1, A1b);
            }
            float lo, hi;
            float* o = out + (R * SEQ + t) * VOC;
            ull A0 = add2(A0a, A0b);
            ull A1 = add2(A1a, A1b);
            unpack2(A0, lo, hi); o[j]       = lo + hi + rb_lo;
            unpack2(A1, lo, hi); o[j + 128] = lo + hi + rb_hi;
        }
        // next timestep's embed-store targets the OTHER buffer; its row barrier
        // orders subsequent writes against these readout reads.
    }

    // ---- h_final (if the harness output includes it after the logits)
    if (out_size >= BATCH * SEQ * VOC + BATCH * HID) {
        float* hf = out + BATCH * SEQ * VOC;
        if (l < 8) {
            hf[R * HID + c0]     = hA;
            hf[R * HID + c0 + 1] = hB;
            hf[R * HID + c0 + 2] = hC;
            hf[R * HID + c0 + 3] = hD;
        }
    }
}

extern "C" void kernel_launch(void* const* d_in, const int* in_sizes, int n_in,
                              void* d_out, int out_size)
{
    (void)in_sizes; (void)n_in;
    const int*   chars   = (const int*)d_in[0];
    const float* hidden  = (const float*)d_in[1];
    const float* embed_w = (const float*)d_in[2];
    const float* Ws      = (const float*)d_in[3];
    const float* ro_w    = (const float*)d_in[4];
    const float* ro_b    = (const float*)d_in[5];
    float* out = (float*)d_out;

    const size_t smem = 64 * 512 * sizeof(float);   // 128KB dynamic
    cudaFuncSetAttribute(rnn_charlm_kernel,
                         cudaFuncAttributeMaxDynamicSharedMemorySize, (int)smem);
    rnn_charlm_kernel<<<NBLK, NTHR, smem>>>(chars, hidden, embed_w, Ws,
                                            ro_w, ro_b, out, out_size);
}

// round 11
// speedup vs baseline: 1.3854x; 1.0532x over previous
#include <cuda_runtime.h>
#include <cstdint>

// RecurrentCharLM: B=256, S=32, H=128, VOCAB=256, DEPTH=100, L=1.
// 128 blocks x 256 threads. Thread = (row, col-quad p, k-quarter s2):
//   FMA phase: 4 cols x 32 k per thread (W in 128 regs, k-packed f32x2),
//   8 LDS.128 per thread per iter (the R9/R10 traffic lever, kept).
// NEW vs R10:
//   * reduce-SCATTER across the 4 k-quarter lanes (xor 8, xor 16): 3 SHFLs
//     instead of 8; each lane ends OWNING one finished column -> 1 STS.32,
//     1-register h state, simpler embed/publish.
//   * row1 warps get a one-time ~240cyc exact-identity delay to offset the
//     two rows' latency phases on each SMSP (retry now that we're
//     latency-exposed, not L1TEX-bound).
// Row-scoped named barriers (bar.sync 1/2, 128).

#define BATCH 256
#define SEQ   32
#define HID   128
#define VOC   256
#define DEPTH_IT 100
#define NBLK  128
#define NTHR  256
#define QP    144          // byte pitch between 32-col segments of h
#define HROW  (4*QP)       // 576 bytes per row buffer

typedef unsigned long long ull;

__device__ __forceinline__ ull pack2(float lo, float hi) {
    ull r; asm("mov.b64 %0, {%1,%2};" : "=l"(r) : "f"(lo), "f"(hi)); return r;
}
__device__ __forceinline__ void unpack2(ull v, float &lo, float &hi) {
    asm("mov.b64 {%0,%1}, %2;" : "=f"(lo), "=f"(hi) : "l"(v));
}
__device__ __forceinline__ ull fma2(ull a, ull b, ull c) {
    ull d; asm("fma.rn.f32x2 %0, %1, %2, %3;" : "=l"(d) : "l"(a), "l"(b), "l"(c));
    return d;
}
__device__ __forceinline__ ull add2(ull a, ull b) {
    ull d; asm("add.rn.f32x2 %0, %1, %2;" : "=l"(d) : "l"(a), "l"(b)); return d;
}
__device__ __forceinline__ ull d2u(double x) { return __double_as_longlong(x); }
__device__ __forceinline__ void row_bar(int id) {
    asm volatile("bar.sync %0, 128;" :: "r"(id) : "memory");
}
__device__ __forceinline__ float red1(ull s) {   // f32x2 -> scalar
    float lo, hi; unpack2(s, lo, hi); return lo + hi;
}

__global__ void __launch_bounds__(NTHR, 1)
rnn_charlm_kernel(const int* __restrict__ chars,
                  const float* __restrict__ hidden,
                  const float* __restrict__ embed_w,
                  const float* __restrict__ Wg,      // (1,128,128): W[k][j]
                  const float* __restrict__ ro_w,    // (256,128)
                  const float* __restrict__ ro_b,    // (256,)
                  float* __restrict__ out, int out_size)
{
    // dynamic smem: ro_w in k-paired transposed layout
    // ro_p[(k>>1)*512 + 2*v + (k&1)] = ro_w[v][k]   (64*512 floats = 128KB)
    extern __shared__ float ro_p[];
    __shared__ __align__(16) char hsraw[2][2][HROW];   // [buf][row][bytes]

    const int tid = threadIdx.x;
    const int row = tid >> 7;               // 0 or 1
    const int w   = (tid >> 5) & 3;         // warp within row
    const int l   = tid & 31;               // lane
    const int s2  = l >> 3;                 // k-quarter 0..3
    const int p   = w * 8 + (l & 7);        // col-quad index 0..31
    const int c0  = 4 * p;                  // first of 4 columns
    const int R   = blockIdx.x * 2 + row;   // global batch row
    const int j   = w * 32 + l;             // readout col id 0..127
    const int ks  = s2 * 32;                // my k-range start
    const int bid = 1 + row;                // named barrier id
    // column this lane OWNS after reduce-scatter: s2 0->+0, 1->+2, 2->+1, 3->+3
    const int colown = c0 + ((s2 & 1) << 1) + (s2 >> 1);
    const bool evenq = (s2 & 1) == 0;
    const bool topq  = (s2 & 2) == 0;

    // ---- W: 4 columns x my 32 k's, k-packed: wA[i] = (W[ks+2i][c0], W[ks+2i+1][c0])
    ull wA[16], wB[16], wC[16], wD[16];
#pragma unroll
    for (int i = 0; i < 16; ++i) {
        const float* r0 = &Wg[(ks + 2 * i) * HID];
        const float* r1 = &Wg[(ks + 2 * i + 1) * HID];
        wA[i] = pack2(r0[c0],     r1[c0]);
        wB[i] = pack2(r0[c0 + 1], r1[c0 + 1]);
        wC[i] = pack2(r0[c0 + 2], r1[c0 + 2]);
        wD[i] = pack2(r0[c0 + 3], r1[c0 + 3]);
    }

    // ---- stage ro_w into smem (once)
    for (int idx = tid; idx < VOC * HID; idx += NTHR) {
        int v = idx / HID, k = idx % HID;
        ro_p[(k >> 1) * 512 + 2 * v + (k & 1)] = ro_w[idx];
    }

    float hval = hidden[R * HID + colown];       // this lane's owned column
    const float rb_lo = ro_b[j];
    const float rb_hi = ro_b[j + 128];
    __syncthreads();   // ro_p staged

    // ---- SYMMETRY BREAKER: row1 delayed ~240 cyc by an exact-identity
    // dependent chain, creating a persistent half-iteration phase offset.
    if (row == 1) {
        const float one = __int_as_float(0x3f800000);
        float d = hval;
#pragma unroll
        for (int i = 0; i < 60; ++i)
            asm volatile("mul.f32 %0, %0, %1;" : "+f"(d) : "f"(one));
        hval = d;
    }

    // smem byte address (within a row buffer) of this lane's owned column
    const int ooff = (colown >> 5) * QP + (colown & 31) * 4;

    int cur = 0;
    for (int t = 0; t < SEQ; ++t) {
        // embed add on the owned column; publish into next buffer
        const int c = chars[R * SEQ + t];
        hval += embed_w[c * HID + colown];
        cur ^= 1;
        *(float*)(hsraw[cur][row] + ooff) = hval;
        row_bar(bid);

        // ---- 100 chained relu(h @ W) iterations
        for (int it = 0; it < DEPTH_IT; ++it) {
            const double2* pa = (const double2*)(hsraw[cur][row] + s2 * QP);
            ull aE = 0, aO = 0, bE = 0, bO = 0, cE = 0, cO = 0, dE = 0, dO = 0;
#pragma unroll
            for (int q = 0; q < 8; ++q) {        // 4 k per q
                double2 x = pa[q];               // k = ks+4q .. ks+4q+3
                aE = fma2(d2u(x.x), wA[2 * q],     aE);
                bE = fma2(d2u(x.x), wB[2 * q],     bE);
                cE = fma2(d2u(x.x), wC[2 * q],     cE);
                dE = fma2(d2u(x.x), wD[2 * q],     dE);
                aO = fma2(d2u(x.y), wA[2 * q + 1], aO);
                bO = fma2(d2u(x.y), wB[2 * q + 1], bO);
                cO = fma2(d2u(x.y), wC[2 * q + 1], cO);
                dO = fma2(d2u(x.y), wD[2 * q + 1], dO);
            }
            float fA = red1(add2(aE, aO));
            float fB = red1(add2(bE, bO));
            float fC = red1(add2(cE, cO));
            float fD = red1(add2(dE, dO));
            // reduce-scatter round 1 (xor 8): even s2 keeps (A,B), odd keeps (C,D)
            float sx = evenq ? fC : fA;
            float sy = evenq ? fD : fB;
            float rx = __shfl_xor_sync(0xffffffffu, sx, 8);
            float ry = __shfl_xor_sync(0xffffffffu, sy, 8);
            float u = (evenq ? fA : fC) + rx;
            float v = (evenq ? fB : fD) + ry;
            // round 2 (xor 16): top keeps u, bottom keeps v
            float sz = topq ? v : u;
            float rz = __shfl_xor_sync(0xffffffffu, sz, 16);
            hval = fmaxf((topq ? u : v) + rz, 0.0f);
            cur ^= 1;
            *(float*)(hsraw[cur][row] + ooff) = hval;
            row_bar(bid);
        }

        // ---- readout: logits[R][v] for v = j and v = j+128 (segment-padded h)
        {
            const char* hb = hsraw[cur][row];
            ull A0a = 0, A0b = 0, A1a = 0, A1b = 0;
#pragma unroll
            for (int q = 0; q < 32; ++q) {       // quad q covers k = 4q..4q+3
                double2 x = *(const double2*)(hb + (q >> 3) * QP + (q & 7) * 16);
                const float* b0 = &ro_p[(2 * q) * 512];
                const float* b1 = &ro_p[(2 * q + 1) * 512];
                ull ra0 = *(const ull*)&b0[2 * j];
                ull rc0 = *(const ull*)&b0[256 + 2 * j];
                ull ra1 = *(const ull*)&b1[2 * j];
                ull rc1 = *(const ull*)&b1[256 + 2 * j];
                A0a = fma2(d2u(x.x), ra0, A0a);
                A1a = fma2(d2u(x.x), rc0, A1a);
                A0b = fma2(d2u(x.y), ra1, A0b);
                A1b = fma2(d2u(x.y), rc1, A1b);
            }
            float lo, hi;
            float* o = out + (R * SEQ + t) * VOC;
            ull A0 = add2(A0a, A0b);
            ull A1 = add2(A1a, A1b);
            unpack2(A0, lo, hi); o[j]       = lo + hi + rb_lo;
            unpack2(A1, lo, hi); o[j + 128] = lo + hi + rb_hi;
        }
        // next timestep's embed-store targets the OTHER buffer; its row barrier
        // orders subsequent writes against these readout reads.
    }

    // ---- h_final (if the harness output includes it after the logits)
    if (out_size >= BATCH * SEQ * VOC + BATCH * HID) {
        float* hf = out + BATCH * SEQ * VOC;
        hf[R * HID + colown] = hval;
    }
}

extern "C" void kernel_launch(void* const* d_in, const int* in_sizes, int n_in,
                              void* d_out, int out_size)
{
    (void)in_sizes; (void)n_in;
    const int*   chars   = (const int*)d_in[0];
    const float* hidden  = (const float*)d_in[1];
    const float* embed_w = (const float*)d_in[2];
    const float* Ws      = (const float*)d_in[3];
    const float* ro_w    = (const float*)d_in[4];
    const float* ro_b    = (const float*)d_in[5];
    float* out = (float*)d_out;

    const size_t smem = 64 * 512 * sizeof(float);   // 128KB dynamic
    cudaFuncSetAttribute(rnn_charlm_kernel,
                         cudaFuncAttributeMaxDynamicSharedMemorySize, (int)smem);
    rnn_charlm_kernel<<<NBLK, NTHR, smem>>>(chars, hidden, embed_w, Ws,
                                            ro_w, ro_b, out, out_size);
}